// round 16
// baseline (speedup 1.0000x reference)
#include <cuda_runtime.h>
#include <cstdint>

// ChessboardLayer: (B,H,W,C)=(32,256,256,32) fp32 space-to-depth into 8x8 cells.
// Pure 4KiB-block transpose:
//   in  chunk id q = br*256 + i*8 + c
//   out chunk id o = br*256 + c*32 + i
//
// R15: last untested cell {256-bit width x block=512 x 8 chunks/CTA}.
// Each CTA owns 8 consecutive OUTPUT chunks -> 32 KiB contiguous write.
// 512 threads; each thread moves 64 B as 2 independent 256-bit pairs
// (words t and t+512 of the CTA's 1024 v8-words). Larger per-CTA burst
// window at the DRAM controller; everything else identical to champion.

__device__ __forceinline__ void ldg256(uint32_t r[8], const void* p) {
    asm volatile("ld.global.nc.v8.b32 {%0,%1,%2,%3,%4,%5,%6,%7}, [%8];"
                 : "=r"(r[0]), "=r"(r[1]), "=r"(r[2]), "=r"(r[3]),
                   "=r"(r[4]), "=r"(r[5]), "=r"(r[6]), "=r"(r[7])
                 : "l"(p));
}
__device__ __forceinline__ void stg256(void* p, const uint32_t r[8]) {
    asm volatile("st.global.v8.b32 [%0], {%1,%2,%3,%4,%5,%6,%7,%8};"
                 :: "l"(p),
                    "r"(r[0]), "r"(r[1]), "r"(r[2]), "r"(r[3]),
                    "r"(r[4]), "r"(r[5]), "r"(r[6]), "r"(r[7])
                 : "memory");
}

__global__ void __launch_bounds__(512, 4)
chessboard_kernel(const float* __restrict__ in, float* __restrict__ out) {
    unsigned obase = blockIdx.x * 8u;    // first output chunk id (chunk = 1024 floats)
    unsigned t     = threadIdx.x;        // 0..511

    // o = obase + k, k=0..7. obase multiple of 8 => i0 in {0,8,16,24},
    // i0+7 <= 31: all 8 share (br, c); i = i0 + k.
    unsigned i0 = obase & 31u;
    unsigned c  = (obase >> 5) & 7u;
    unsigned br = obase >> 8;
    unsigned qbase = br * 256u + i0 * 8u + c;   // input chunk for k=0; +8 per k

    // CTA moves 8192 floats = 1024 v8-words; thread t handles words t, t+512.
    // word w: k = w >> 7 (0..7), j = w & 127.
    unsigned k0 = t >> 7, j0 = t & 127u;        // w0 = t      -> k0 in {0..3}
    unsigned k1 = k0 + 4u;                      // w1 = t+512  -> k1 in {4..7}

    const float* pi0 = in + (size_t)(qbase + k0 * 8u) * 1024u + j0 * 8u;
    const float* pi1 = in + (size_t)(qbase + k1 * 8u) * 1024u + j0 * 8u;

    uint32_t a[8], b[8];
    ldg256(a, pi0);
    ldg256(b, pi1);

    float* po0 = out + (size_t)(obase + k0) * 1024u + j0 * 8u;
    float* po1 = out + (size_t)(obase + k1) * 1024u + j0 * 8u;
    stg256(po0, a);
    stg256(po1, b);
}

extern "C" void kernel_launch(void* const* d_in, const int* in_sizes, int n_in,
                              void* d_out, int out_size) {
    const float* in  = (const float*)d_in[0];
    float*       out = (float*)d_out;
    // 65536 output chunks / 8 per CTA = 8192 CTAs
    chessboard_kernel<<<8192, 512>>>(in, out);
}

// round 17
// speedup vs baseline: 1.0016x; 1.0016x over previous
#include <cuda_runtime.h>
#include <cstdint>

// ChessboardLayer: (B,H,W,C)=(32,256,256,32) fp32 space-to-depth into 8x8 cells.
// Pure 4KiB-block transpose:
//   in  chunk id q = br*256 + i*8 + c
//   out chunk id o = br*256 + c*32 + i
//
// R16: continue the R15 trend (larger per-CTA write burst window):
// block=1024, 16 consecutive OUTPUT chunks per CTA -> 64 KiB contiguous
// write window. 256-bit accesses, 2 independent pairs per thread.
// R15 (block=512, 32 KiB window) measured 73.95us / DRAM 82.1% — best yet.

__device__ __forceinline__ void ldg256(uint32_t r[8], const void* p) {
    asm volatile("ld.global.nc.v8.b32 {%0,%1,%2,%3,%4,%5,%6,%7}, [%8];"
                 : "=r"(r[0]), "=r"(r[1]), "=r"(r[2]), "=r"(r[3]),
                   "=r"(r[4]), "=r"(r[5]), "=r"(r[6]), "=r"(r[7])
                 : "l"(p));
}
__device__ __forceinline__ void stg256(void* p, const uint32_t r[8]) {
    asm volatile("st.global.v8.b32 [%0], {%1,%2,%3,%4,%5,%6,%7,%8};"
                 :: "l"(p),
                    "r"(r[0]), "r"(r[1]), "r"(r[2]), "r"(r[3]),
                    "r"(r[4]), "r"(r[5]), "r"(r[6]), "r"(r[7])
                 : "memory");
}

__global__ void __launch_bounds__(1024, 2)
chessboard_kernel(const float* __restrict__ in, float* __restrict__ out) {
    unsigned obase = blockIdx.x * 16u;   // first output chunk id (chunk = 1024 floats)
    unsigned t     = threadIdx.x;        // 0..1023

    // o = obase + k, k=0..15. obase multiple of 16 => i0 in {0,16},
    // i0+15 <= 31: all 16 share (br, c); i = i0 + k.
    unsigned i0 = obase & 31u;
    unsigned c  = (obase >> 5) & 7u;
    unsigned br = obase >> 8;
    unsigned qbase = br * 256u + i0 * 8u + c;   // input chunk for k=0; +8 per k

    // CTA moves 16384 floats = 2048 v8-words; thread t handles words t, t+1024.
    // word w: k = w >> 7 (0..15), j = w & 127.
    unsigned k0 = t >> 7, j0 = t & 127u;        // w0 = t       -> k0 in {0..7}
    unsigned k1 = k0 + 8u;                      // w1 = t+1024  -> k1 in {8..15}

    const float* pi0 = in + (size_t)(qbase + k0 * 8u) * 1024u + j0 * 8u;
    const float* pi1 = in + (size_t)(qbase + k1 * 8u) * 1024u + j0 * 8u;

    uint32_t a[8], b[8];
    ldg256(a, pi0);
    ldg256(b, pi1);

    float* po0 = out + (size_t)(obase + k0) * 1024u + j0 * 8u;
    float* po1 = out + (size_t)(obase + k1) * 1024u + j0 * 8u;
    stg256(po0, a);
    stg256(po1, b);
}

extern "C" void kernel_launch(void* const* d_in, const int* in_sizes, int n_in,
                              void* d_out, int out_size) {
    const float* in  = (const float*)d_in[0];
    float*       out = (float*)d_out;
    // 65536 output chunks / 16 per CTA = 4096 CTAs
    chessboard_kernel<<<4096, 1024>>>(in, out);
}